// round 2
// baseline (speedup 1.0000x reference)
#include <cuda_runtime.h>
#include <math.h>

// Problem constants (DiceLoss: logits [8,19,512,512] f32, targets [8,512,512] int32 on-device)
#define NC 19
#define IGNORE_INDEX 255
static const long long HW = 512LL * 512LL;   // per-image spatial size

// Scratch: probs_sum[0..18], inter[19..37], cnt[38..56], valid_count[57]
__device__ float g_acc[3 * NC + 1];

__global__ void dice_zero_kernel() {
    int i = threadIdx.x;
    if (i < 3 * NC + 1) g_acc[i] = 0.0f;
}

__global__ __launch_bounds__(256) void dice_main_kernel(
    const float* __restrict__ logits,
    const int* __restrict__ targets,
    long long npix)
{
    __shared__ float s_inter[NC];
    __shared__ float s_cnt[NC];
    __shared__ float s_psum[NC];
    __shared__ float s_valid;

    const int tid = threadIdx.x;
    if (tid < NC) { s_inter[tid] = 0.0f; s_cnt[tid] = 0.0f; s_psum[tid] = 0.0f; }
    if (tid == 0) s_valid = 0.0f;
    __syncthreads();

    float acc[NC];
#pragma unroll
    for (int c = 0; c < NC; c++) acc[c] = 0.0f;
    float vcnt = 0.0f;

    const long long stride = (long long)gridDim.x * blockDim.x;
    for (long long p = (long long)blockIdx.x * blockDim.x + tid; p < npix; p += stride) {
        const int t = targets[p];
        if (t < 0 || t >= NC) continue;   // IGNORE_INDEX (255) or anything invalid

        const long long b  = p >> 18;            // p / HW   (HW = 2^18)
        const long long hw = p & (HW - 1);       // p % HW
        const float* base = logits + (b * NC) * HW + hw;

        float e[NC];
        float m = -INFINITY;
#pragma unroll
        for (int c = 0; c < NC; c++) {
            e[c] = base[(long long)c * HW];
            m = fmaxf(m, e[c]);
        }
        float s = 0.0f;
#pragma unroll
        for (int c = 0; c < NC; c++) {
            e[c] = __expf(e[c] - m);
            s += e[c];
        }
        const float inv = __frcp_rn(s);

        float gathered = 0.0f;
#pragma unroll
        for (int c = 0; c < NC; c++) {
            const float pr = e[c] * inv;
            acc[c] += pr;
            if (c == t) gathered = pr;
        }
        vcnt += 1.0f;
        atomicAdd(&s_inter[t], gathered);
        atomicAdd(&s_cnt[t], 1.0f);
    }

    // Warp-reduce the register accumulators, then one shared atomic per warp.
#pragma unroll
    for (int c = 0; c < NC; c++) {
        float v = acc[c];
#pragma unroll
        for (int o = 16; o > 0; o >>= 1) v += __shfl_xor_sync(0xffffffffu, v, o);
        if ((tid & 31) == 0) atomicAdd(&s_psum[c], v);
    }
    {
        float v = vcnt;
#pragma unroll
        for (int o = 16; o > 0; o >>= 1) v += __shfl_xor_sync(0xffffffffu, v, o);
        if ((tid & 31) == 0) atomicAdd(&s_valid, v);
    }
    __syncthreads();

    // One global atomic per class per block (plus one for the valid count).
    if (tid < NC) {
        atomicAdd(&g_acc[tid],           s_psum[tid]);
        atomicAdd(&g_acc[NC + tid],      s_inter[tid]);
        atomicAdd(&g_acc[2 * NC + tid],  s_cnt[tid]);
    }
    if (tid == 0) atomicAdd(&g_acc[3 * NC], s_valid);
}

__global__ void dice_finalize_kernel(float* __restrict__ out) {
    const int c = threadIdx.x;
    float contrib = 0.0f;
    if (c < NC) {
        const float psum  = g_acc[c];
        const float inter = g_acc[NC + c];
        const float cnt   = g_acc[2 * NC + c];
        const float dice  = (2.0f * inter + 1.0f) / (psum + cnt + 1.0f);
        contrib = 1.0f - dice;
    }
#pragma unroll
    for (int o = 16; o > 0; o >>= 1) contrib += __shfl_xor_sync(0xffffffffu, contrib, o);
    if (c == 0) {
        const float valid = g_acc[3 * NC];
        out[0] = (valid > 0.0f) ? (contrib / (float)NC) : 0.0f;
    }
}

extern "C" void kernel_launch(void* const* d_in, const int* in_sizes, int n_in,
                              void* d_out, int out_size) {
    const float* logits  = (const float*)d_in[0];
    const int*   targets = (const int*)d_in[1];
    float* out = (float*)d_out;

    const long long npix = (long long)in_sizes[1];   // B*H*W = 2,097,152

    dice_zero_kernel<<<1, 64>>>();
    dice_main_kernel<<<592, 256>>>(logits, targets, npix);
    dice_finalize_kernel<<<1, 32>>>(out);
}